// round 16
// baseline (speedup 1.0000x reference)
#include <cuda_runtime.h>
#include <cuda_fp16.h>
#include <math.h>
#include <stdint.h>

#define NLAYER 24
#define NHEAD  16
#define DMODEL 1024
#define HDIM   64
#define VOCAB  50257
#define BATCH  2
#define SEQ    1024
#define BTOK   (BATCH*SEQ)
#define FFDIM  4096
#define D3     (3*DMODEL)

__device__ float g_x  [BTOK*DMODEL];
__device__ __half g_qkv[BTOK*D3];
__device__ __half g_h [BTOK*DMODEL];
__device__ __half g_y [BTOK*DMODEL];
__device__ __half g_ff[BTOK*FFDIM];
__device__ __half g_wq[(size_t)NLAYER*DMODEL*D3];
__device__ __half g_wa[(size_t)NLAYER*DMODEL*DMODEL];
__device__ __half g_wf[(size_t)NLAYER*DMODEL*FFDIM];
__device__ __half g_wp[(size_t)NLAYER*FFDIM*DMODEL];
__device__ __half g_we[(size_t)VOCAB*DMODEL];

__device__ __forceinline__ uint32_t smem_u32(const void* p){
    uint32_t a;
    asm("{ .reg .u64 t; cvta.to.shared.u64 t, %1; cvt.u32.u64 %0, t; }" : "=r"(a) : "l"(p));
    return a;
}
#define LDSM4(r0,r1,r2,r3,a) asm volatile("ldmatrix.sync.aligned.m8n8.x4.shared.b16 {%0,%1,%2,%3},[%4];":"=r"(r0),"=r"(r1),"=r"(r2),"=r"(r3):"r"(a))
#define MMA_F16(c,a,b) asm volatile( \
    "mma.sync.aligned.m16n8k16.row.col.f32.f16.f16.f32 {%0,%1,%2,%3},{%4,%5,%6,%7},{%8,%9},{%0,%1,%2,%3};" \
    :"+f"((c)[0]),"+f"((c)[1]),"+f"((c)[2]),"+f"((c)[3]) \
    :"r"((a)[0]),"r"((a)[1]),"r"((a)[2]),"r"((a)[3]),"r"((b)[0]),"r"((b)[1]))
#define CPASYNC16(sa,gp) asm volatile("cp.async.cg.shared.global [%0],[%1],16;"::"r"(sa),"l"(gp))
#define CPCOMMIT() asm volatile("cp.async.commit_group;":::"memory")
#define CPWAIT0()  asm volatile("cp.async.wait_group 0;":::"memory")

__device__ __forceinline__ float gelu_f(float x){
    float x3=x*x*x;
    return 0.5f*x*(1.f+tanhf(0.7978845608028654f*(x+0.044715f*x3)));
}
__device__ __forceinline__ uint32_t pack2h(__half a, __half b){
    return ((uint32_t)__half_as_ushort(b)<<16)|__half_as_ushort(a);
}

__global__ __launch_bounds__(256) void embed_kernel(
    const int* __restrict__ idx, const float* __restrict__ wte,
    const float* __restrict__ wpe, float* __restrict__ x)
{
    int i=blockIdx.x*256+threadIdx.x, tok=i>>8, c=i&255, t=tok&(SEQ-1);
    int id=idx[tok];
    float4 a=((const float4*)(wte+(size_t)id*DMODEL))[c];
    float4 p=((const float4*)(wpe+(size_t)t*DMODEL))[c];
    a.x+=p.x; a.y+=p.y; a.z+=p.z; a.w+=p.w;
    ((float4*)x)[i]=a;
}

__global__ __launch_bounds__(256) void ln_kernel(
    const float* __restrict__ x, const float* __restrict__ w, const float* __restrict__ b,
    __half* __restrict__ oh)
{
    int row=blockIdx.x, tid=threadIdx.x;
    float4 v=((const float4*)(x+(size_t)row*DMODEL))[tid];
    float s=v.x+v.y+v.z+v.w, sq=v.x*v.x+v.y*v.y+v.z*v.z+v.w*v.w;
    #pragma unroll
    for(int o=16;o>0;o>>=1){ s+=__shfl_xor_sync(~0u,s,o); sq+=__shfl_xor_sync(~0u,sq,o); }
    __shared__ float ss[8],sqs[8];
    if((tid&31)==0){ ss[tid>>5]=s; sqs[tid>>5]=sq; }
    __syncthreads();
    float st=0,sqt=0;
    #pragma unroll
    for(int i=0;i<8;i++){ st+=ss[i]; sqt+=sqs[i]; }
    float mean=st*(1.f/DMODEL), var=sqt*(1.f/DMODEL)-mean*mean, inv=rsqrtf(var+1e-5f);
    float4 wv=((const float4*)w)[tid], bv=((const float4*)b)[tid];
    float o0=(v.x-mean)*inv*wv.x+bv.x, o1=(v.y-mean)*inv*wv.y+bv.y;
    float o2=(v.z-mean)*inv*wv.z+bv.z, o3=(v.w-mean)*inv*wv.w+bv.w;
    size_t base=(size_t)row*DMODEL+tid*4;
    *(uint2*)(oh+base)=make_uint2(
        pack2h(__float2half(o0),__float2half(o1)),
        pack2h(__float2half(o2),__float2half(o3)));
}

// W[K][N] (layer l) -> fp16 [N][K]
__global__ void wconv_t(const float* __restrict__ W, __half* __restrict__ O, int K, int N)
{
    __shared__ float t[32][33];
    int l=blockIdx.z;
    const float* Wl=W+(size_t)l*K*N;
    __half* Ol=O+(size_t)l*K*N;
    int n0=blockIdx.x*32, k0=blockIdx.y*32, tx=threadIdx.x, ty=threadIdx.y;
    #pragma unroll
    for(int i=0;i<4;i++) t[ty+8*i][tx]=Wl[(size_t)(k0+ty+8*i)*N+n0+tx];
    __syncthreads();
    #pragma unroll
    for(int i=0;i<4;i++)
        Ol[(size_t)(n0+ty+8*i)*K+k0+tx]=__float2half(t[tx][ty+8*i]);
}

__global__ __launch_bounds__(256) void wte_conv(
    const float* __restrict__ w, __half* __restrict__ o)
{
    size_t base=(size_t)blockIdx.x*DMODEL+threadIdx.x*4;
    float4 v=*(const float4*)(w+base);
    *(uint2*)(o+base)=make_uint2(
        pack2h(__float2half(v.x),__float2half(v.y)),
        pack2h(__float2half(v.z),__float2half(v.w)));
}

// ---- single-pass fp16 GEMM, templated CTA M-tile (BM = 128 or 64) -------
// act 0: bias->f32  1: bias+res->f32  2: bias+gelu->fp16  3: plain guarded f32
// act 4: bias->fp16 with 0.125 scale on cols<DMODEL (qkv output)
#define GST   40
template<int BM>
__global__ __launch_bounds__(256,2) void gemm_mma(
    const __half* __restrict__ A, const __half* __restrict__ B,
    const float* __restrict__ bias, const float* __restrict__ res,
    float* __restrict__ Cf, __half* __restrict__ Ch,
    int N, int K, int act)
{
    constexpr int NT  = (BM==128)?8:4;          // n-subtiles per warp
    constexpr int ASB = BM*GST*2;               // A slab bytes
    constexpr int BSB = 128*GST*2;              // B slab bytes
    extern __shared__ __half sm2[];
    const uint32_t smA = smem_u32(sm2);
    const uint32_t smB = smA + 2*ASB;
    const int tid=threadIdx.x, wid=tid>>5, lane=tid&31;
    const int bm=blockIdx.x*BM, bn=blockIdx.y*128;
    const int wm=(BM==128)?((wid&3)*32):((wid&1)*32);
    const int wn=(BM==128)?((wid>>2)*64):((wid>>1)*32);
    const int row2=tid>>2, ch=tid&3;

    float acc[2][NT][4];
    #pragma unroll
    for(int i=0;i<2;i++)
        #pragma unroll
        for(int j=0;j<NT;j++)
            #pragma unroll
            for(int k=0;k<4;k++) acc[i][j][k]=0.f;

    const uint32_t a_base  = smA + (uint32_t)(((wm+(lane&15))*GST + (lane>>4)*8)*2);
    const uint32_t b4_base = smB + (uint32_t)(((wn+(lane&7)+((lane>>4)&1)*8)*GST + ((lane>>3)&1)*8)*2);
    const int KS = K>>5;

    auto load_stage=[&](int c,int buf){
        const size_t gk=(size_t)c*32 + ch*8;
        #pragma unroll
        for(int hf=0;hf<BM/64;hf++){
            int r=row2+hf*64;
            uint32_t sa = smA + buf*ASB + (uint32_t)((r*GST+ch*8)*2);
            CPASYNC16(sa, A+(size_t)(bm+r)*K+gk);
        }
        #pragma unroll
        for(int hf=0;hf<2;hf++){
            int r=row2+hf*64;
            int gn=bn+r; size_t gs=(gn<N)?(size_t)gn:0;
            uint32_t sb = smB + buf*BSB + (uint32_t)((r*GST+ch*8)*2);
            CPASYNC16(sb, B+gs*K+gk);
        }
    };

    load_stage(0,0); CPCOMMIT(); CPWAIT0();
    __syncthreads();

    for(int c=0;c<KS;c++){
        const int buf=c&1;
        if(c+1<KS){ load_stage(c+1,buf^1); CPCOMMIT(); }
        const uint32_t ab=a_base+buf*ASB, bb=b4_base+buf*BSB;
        #pragma unroll
        for(int ks=0;ks<2;ks++){
            uint32_t Ah[2][4],Bh[NT][2];
            #pragma unroll
            for(int mt=0;mt<2;mt++){
                uint32_t ad=ab+mt*(16*GST*2)+ks*32;
                LDSM4(Ah[mt][0],Ah[mt][1],Ah[mt][2],Ah[mt][3], ad);
            }
            #pragma unroll
            for(int np=0;np<NT/2;np++){
                uint32_t bd=bb+np*(16*GST*2)+ks*32;
                LDSM4(Bh[2*np][0],Bh[2*np][1],Bh[2*np+1][0],Bh[2*np+1][1], bd);
            }
            #pragma unroll
            for(int mt=0;mt<2;mt++)
                #pragma unroll
                for(int nt=0;nt<NT;nt++)
                    MMA_F16(acc[mt][nt], Ah[mt], Bh[nt]);
        }
        if(c+1<KS) CPWAIT0();
        __syncthreads();
    }

    const int g=lane>>2, ct=lane&3;
    #pragma unroll
    for(int mt=0;mt<2;mt++){
        #pragma unroll
        for(int nt=0;nt<NT;nt++){
            int r0=bm+wm+mt*16+g, r1=r0+8;
            int col=bn+wn+nt*8+ct*2;
            float c0=acc[mt][nt][0], c1=acc[mt][nt][1];
            float c2=acc[mt][nt][2], c3=acc[mt][nt][3];
            if(act==3){
                if(col<N)   Cf[(size_t)r0*N+col]=c0;
                if(col+1<N) Cf[(size_t)r0*N+col+1]=c1;
                if(col<N)   Cf[(size_t)r1*N+col]=c2;
                if(col+1<N) Cf[(size_t)r1*N+col+1]=c3;
            } else {
                float b0=bias[col], b1=bias[col+1];
                c0+=b0; c1+=b1; c2+=b0; c3+=b1;
                if(act==1){
                    float2 q0=*(const float2*)(res+(size_t)r0*N+col);
                    float2 q1=*(const float2*)(res+(size_t)r1*N+col);
                    c0+=q0.x; c1+=q0.y; c2+=q1.x; c3+=q1.y;
                    *(float2*)(Cf+(size_t)r0*N+col)=make_float2(c0,c1);
                    *(float2*)(Cf+(size_t)r1*N+col)=make_float2(c2,c3);
                } else if(act==0){
                    *(float2*)(Cf+(size_t)r0*N+col)=make_float2(c0,c1);
                    *(float2*)(Cf+(size_t)r1*N+col)=make_float2(c2,c3);
                } else if(act==4){
                    float sc=(col<DMODEL)?0.125f:1.f;
                    *(uint32_t*)(Ch+(size_t)r0*N+col)=pack2h(__float2half(c0*sc),__float2half(c1*sc));
                    *(uint32_t*)(Ch+(size_t)r1*N+col)=pack2h(__float2half(c2*sc),__float2half(c3*sc));
                } else { // act==2 gelu -> fp16
                    c0=gelu_f(c0); c1=gelu_f(c1); c2=gelu_f(c2); c3=gelu_f(c3);
                    *(uint32_t*)(Ch+(size_t)r0*N+col)=pack2h(__float2half(c0),__float2half(c1));
                    *(uint32_t*)(Ch+(size_t)r1*N+col)=pack2h(__float2half(c2),__float2half(c3));
                }
            }
        }
    }
}

#define GSMEM_128 (2*(128*GST*2)+2*(128*GST*2))
#define GSMEM_64  (2*(64*GST*2) +2*(128*GST*2))

// ---- fp16 single-pass tensor-core flash attention ------------------------
#define AT_STR 72
#define AT_TILE (64*AT_STR)
#define AT_SMEM (3*AT_TILE*2)
__global__ __launch_bounds__(128) void attn_tc(
    const __half* __restrict__ qkv, __half* __restrict__ y)
{
    extern __shared__ __half sma[];
    __half *Qs=sma, *Ks=sma+AT_TILE, *Vt=sma+2*AT_TILE;
    const int qb=blockIdx.x, h=blockIdx.y, b=blockIdx.z;
    const int tid=threadIdx.x, wid=tid>>5, lane=tid&31;
    const int q0=qb*64;
    const __half* base=qkv+(size_t)b*SEQ*D3;

    #pragma unroll
    for(int i=0;i<4;i++){
        int idx=tid+128*i, r=idx>>3, ch=idx&7;
        uint4 v=*(const uint4*)(base+(size_t)(q0+r)*D3+h*HDIM+ch*8);
        *(uint4*)(Qs+r*AT_STR+ch*8)=v;
    }

    const int g=lane>>2, ct=lane&3;
    float o[8][4];
    #pragma unroll
    for(int nt=0;nt<8;nt++){ o[nt][0]=0.f;o[nt][1]=0.f;o[nt][2]=0.f;o[nt][3]=0.f; }
    float m0=-1e30f,m1=-1e30f,l0=0.f,l1=0.f;

    const uint32_t qa  = smem_u32(Qs) + (uint32_t)(((wid*16+(lane&15))*AT_STR + (lane>>4)*8)*2);
    const uint32_t kb4 = smem_u32(Ks) + (uint32_t)((((lane&7)+((lane>>4)&1)*8)*AT_STR + ((lane>>3)&1)*8)*2);
    const uint32_t vb4 = smem_u32(Vt) + (uint32_t)((((lane&7)+((lane>>4)&1)*8)*AT_STR + ((lane>>3)&1)*8)*2);

    for(int kt=0;kt<=qb;kt++){
        __syncthreads();
        const int ks0=kt*64;
        #pragma unroll
        for(int i=0;i<4;i++){
            int idx=tid+128*i, r=idx>>3, ch=idx&7;
            uint4 v=*(const uint4*)(base+(size_t)(ks0+r)*D3+DMODEL+h*HDIM+ch*8);
            *(uint4*)(Ks+r*AT_STR+ch*8)=v;
        }
        #pragma unroll
        for(int i=0;i<8;i++){
            int idx=tid+128*i, r=idx>>4, c=(idx&15)*4;
            uint2 v=*(const uint2*)(base+(size_t)(ks0+r)*D3+2*DMODEL+h*HDIM+c);
            const __half* pv=(const __half*)&v;
            Vt[(c+0)*AT_STR+r]=pv[0]; Vt[(c+1)*AT_STR+r]=pv[1];
            Vt[(c+2)*AT_STR+r]=pv[2]; Vt[(c+3)*AT_STR+r]=pv[3];
        }
        __syncthreads();

        float S[8][4];
        #pragma unroll
        for(int nt=0;nt<8;nt++){ S[nt][0]=0.f;S[nt][1]=0.f;S[nt][2]=0.f;S[nt][3]=0.f; }
        #pragma unroll
        for(int ks=0;ks<4;ks++){
            uint32_t Aq[4],KF[8][2];
            LDSM4(Aq[0],Aq[1],Aq[2],Aq[3], qa + ks*32);
            #pragma unroll
            for(int np=0;np<4;np++){
                uint32_t kd = kb4 + np*(16*AT_STR*2) + ks*32;
                LDSM4(KF[2*np][0],KF[2*np][1],KF[2*np+1][0],KF[2*np+1][1], kd);
            }
            #pragma unroll
            for(int nt=0;nt<8;nt++) MMA_F16(S[nt], Aq, KF[nt]);
        }
        if(kt==qb){
            const int r0=q0+wid*16+g, r1=r0+8;
            #pragma unroll
            for(int nt=0;nt<8;nt++){
                int c0=ks0+nt*8+ct*2;
                if(c0>r0)   S[nt][0]=-1e30f;
                if(c0+1>r0) S[nt][1]=-1e30f;
                if(c0>r1)   S[nt][2]=-1e30f;
                if(c0+1>r1) S[nt][3]=-1e30f;
            }
        }
        float rm0=-1e30f, rm1=-1e30f;
        #pragma unroll
        for(int nt=0;nt<8;nt++){
            rm0=fmaxf(rm0,fmaxf(S[nt][0],S[nt][1]));
            rm1=fmaxf(rm1,fmaxf(S[nt][2],S[nt][3]));
        }
        rm0=fmaxf(rm0,__shfl_xor_sync(~0u,rm0,1)); rm0=fmaxf(rm0,__shfl_xor_sync(~0u,rm0,2));
        rm1=fmaxf(rm1,__shfl_xor_sync(~0u,rm1,1)); rm1=fmaxf(rm1,__shfl_xor_sync(~0u,rm1,2));
        float mn0=fmaxf(m0,rm0), mn1=fmaxf(m1,rm1);
        float al0=__expf(m0-mn0), al1=__expf(m1-mn1);
        m0=mn0; m1=mn1;
        float rs0=0.f, rs1=0.f;
        uint32_t ph[4][4];
        #pragma unroll
        for(int j=0;j<8;j++){
            float p0=__expf(S[j][0]-mn0), p1=__expf(S[j][1]-mn0);
            float p2=__expf(S[j][2]-mn1), p3=__expf(S[j][3]-mn1);
            rs0+=p0+p1; rs1+=p2+p3;
            ph[j>>1][(j&1)*2]  =pack2h(__float2half(p0),__float2half(p1));
            ph[j>>1][(j&1)*2+1]=pack2h(__float2half(p2),__float2half(p3));
        }
        rs0+=__shfl_xor_sync(~0u,rs0,1); rs0+=__shfl_xor_sync(~0u,rs0,2);
        rs1+=__shfl_xor_sync(~0u,rs1,1); rs1+=__shfl_xor_sync(~0u,rs1,2);
        l0=l0*al0+rs0; l1=l1*al1+rs1;
        #pragma unroll
        for(int nt=0;nt<8;nt++){
            o[nt][0]*=al0; o[nt][1]*=al0; o[nt][2]*=al1; o[nt][3]*=al1;
        }
        #pragma unroll
        for(int kk=0;kk<4;kk++){
            uint32_t VF[8][2];
            #pragma unroll
            for(int np=0;np<4;np++){
                uint32_t vd = vb4 + np*(16*AT_STR*2) + kk*32;
                LDSM4(VF[2*np][0],VF[2*np][1],VF[2*np+1][0],VF[2*np+1][1], vd);
            }
            #pragma unroll
            for(int nt=0;nt<8;nt++) MMA_F16(o[nt], ph[kk], VF[nt]);
        }
    }
    const float i0=1.f/l0, i1=1.f/l1;
    const size_t r0=(size_t)(b*SEQ+q0+wid*16+g), r1=r0+8;
    #pragma unroll
    for(int nt=0;nt<8;nt++){
        int col=h*HDIM+nt*8+ct*2;
        *(uint32_t*)(y+r0*DMODEL+col)=pack2h(__float2half(o[nt][0]*i0),__float2half(o[nt][1]*i0));
        *(uint32_t*)(y+r1*DMODEL+col)=pack2h(__float2half(o[nt][2]*i1),__float2half(o[nt][3]*i1));
    }
}

extern "C" void kernel_launch(void* const* d_in, const int* in_sizes, int n_in,
                              void* d_out, int out_size)
{
    (void)in_sizes;(void)n_in;(void)out_size;
    const int*   idx   =(const int*)  d_in[0];
    const float* wte   =(const float*)d_in[1];
    const float* wpe   =(const float*)d_in[2];
    const float* ln1_w =(const float*)d_in[3];
    const float* ln1_b =(const float*)d_in[4];
    const float* aw    =(const float*)d_in[5];
    const float* ab    =(const float*)d_in[6];
    const float* pw    =(const float*)d_in[7];
    const float* pb    =(const float*)d_in[8];
    const float* ln2_w =(const float*)d_in[9];
    const float* ln2_b =(const float*)d_in[10];
    const float* fw    =(const float*)d_in[11];
    const float* fb    =(const float*)d_in[12];
    const float* ow    =(const float*)d_in[13];
    const float* ob    =(const float*)d_in[14];
    const float* lnf_w =(const float*)d_in[15];
    const float* lnf_b =(const float*)d_in[16];
    float* out=(float*)d_out;

    cudaFuncSetAttribute(attn_tc,       cudaFuncAttributeMaxDynamicSharedMemorySize, AT_SMEM);
    cudaFuncSetAttribute(gemm_mma<128>, cudaFuncAttributeMaxDynamicSharedMemorySize, GSMEM_128);
    cudaFuncSetAttribute(gemm_mma<64>,  cudaFuncAttributeMaxDynamicSharedMemorySize, GSMEM_64);

    float *x;
    __half *qkv,*h,*y,*ff;
    __half *wq,*wa,*wf,*wp,*we;
    cudaGetSymbolAddress((void**)&x,g_x);    cudaGetSymbolAddress((void**)&qkv,g_qkv);
    cudaGetSymbolAddress((void**)&h,g_h);    cudaGetSymbolAddress((void**)&y,g_y);
    cudaGetSymbolAddress((void**)&ff,g_ff);
    cudaGetSymbolAddress((void**)&wq,g_wq);  cudaGetSymbolAddress((void**)&wa,g_wa);
    cudaGetSymbolAddress((void**)&wf,g_wf);  cudaGetSymbolAddress((void**)&wp,g_wp);
    cudaGetSymbolAddress((void**)&we,g_we);

    dim3 wb(32,8);
    wconv_t<<<dim3(D3/32,   DMODEL/32, NLAYER), wb>>>(aw, wq, DMODEL, D3);
    wconv_t<<<dim3(DMODEL/32,DMODEL/32,NLAYER), wb>>>(pw, wa, DMODEL, DMODEL);
    wconv_t<<<dim3(FFDIM/32, DMODEL/32,NLAYER), wb>>>(fw, wf, DMODEL, FFDIM);
    wconv_t<<<dim3(DMODEL/32,FFDIM/32, NLAYER), wb>>>(ow, wp, FFDIM, DMODEL);
    wte_conv<<<VOCAB,256>>>(wte, we);

    embed_kernel<<<BTOK*DMODEL/1024,256>>>(idx, wte, wpe, x);

    for(int l=0;l<NLAYER;l++){
        ln_kernel<<<BTOK,256>>>(x, ln1_w+(size_t)l*DMODEL, ln1_b+(size_t)l*DMODEL, h);
        gemm_mma<64><<<dim3(BTOK/64,D3/128),256,GSMEM_64>>>(
            h, wq+(size_t)l*DMODEL*D3,
            ab+(size_t)l*D3, nullptr, nullptr, qkv, D3, DMODEL, 4);
        attn_tc<<<dim3(SEQ/64,NHEAD,BATCH),128,AT_SMEM>>>(qkv, y);
        gemm_mma<64><<<dim3(BTOK/64,DMODEL/128),256,GSMEM_64>>>(
            y, wa+(size_t)l*DMODEL*DMODEL,
            pb+(size_t)l*DMODEL, x, x, nullptr, DMODEL, DMODEL, 1);
        ln_kernel<<<BTOK,256>>>(x, ln2_w+(size_t)l*DMODEL, ln2_b+(size_t)l*DMODEL, h);
        gemm_mma<128><<<dim3(BTOK/128,FFDIM/128),256,GSMEM_128>>>(
            h, wf+(size_t)l*DMODEL*FFDIM,
            fb+(size_t)l*FFDIM, nullptr, nullptr, ff, FFDIM, DMODEL, 2);
        gemm_mma<64><<<dim3(BTOK/64,DMODEL/128),256,GSMEM_64>>>(
            ff, wp+(size_t)l*FFDIM*DMODEL,
            ob+(size_t)l*DMODEL, x, x, nullptr, DMODEL, FFDIM, 1);
    }
    ln_kernel<<<BTOK,256>>>(x, lnf_w, lnf_b, h);
    gemm_mma<128><<<dim3(BTOK/128,(VOCAB+127)/128),256,GSMEM_128>>>(
        h, we, nullptr, nullptr, out, nullptr, VOCAB, DMODEL, 3);
}